// round 6
// baseline (speedup 1.0000x reference)
#include <cuda_runtime.h>

#define NTOK   2048
#define NH     32
#define NKV    8
#define HD     128
#define BLKSZ  64
#define LOCALB 16
#define VERTS  8
#define NB     (NTOK/BLKSZ)
#define QSCALE 0.08838834764831845f

typedef unsigned long long u64;

__device__ __forceinline__ u64 pack2(float lo, float hi) {
    u64 r; asm("mov.b64 %0, {%1,%2};" : "=l"(r) : "f"(lo), "f"(hi)); return r;
}
__device__ __forceinline__ void unpack2(u64 v, float& lo, float& hi) {
    asm("mov.b64 {%0,%1}, %2;" : "=f"(lo), "=f"(hi) : "l"(v));
}
__device__ __forceinline__ u64 ffma2(u64 a, u64 b, u64 c) {
    u64 d; asm("fma.rn.f32x2 %0, %1, %2, %3;" : "=l"(d) : "l"(a), "l"(b), "l"(c)); return d;
}
__device__ __forceinline__ u64 fmul2(u64 a, u64 b) {
    u64 d; asm("mul.rn.f32x2 %0, %1, %2;" : "=l"(d) : "l"(a), "l"(b)); return d;
}

// One CTA = one (head, query-block). 256 threads as 16x16 grid:
//   ty = tid>>4 owns S/O rows ty*4..ty*4+3
//   tx = tid&15 owns S cols {tx, tx+16, tx+32, tx+48}, O cols {4tx..4tx+3, 64+4tx..64+4tx+3}
// Q/K/V/P tiles live in smem with a 16B-granule XOR swizzle (granule ^ (row&7))
// so all LDS.128 in both GEMMs are bank-conflict-free.
__global__ void __launch_bounds__(256, 2)
bsattn_kernel(const float* __restrict__ gQ, const float* __restrict__ gK,
              const float* __restrict__ gV, float* __restrict__ gO)
{
    extern __shared__ float smem[];
    float* sQ = smem;           // 64*128
    float* sK = sQ + 8192;      // 64*128
    float* sV = sK + 8192;      // 64*128
    float* sP = sV + 8192;      // 64*64

    const int qb  = blockIdx.x;
    const int h   = blockIdx.y;
    const int tid = threadIdx.x;
    const int ty  = tid >> 4;
    const int tx  = tid & 15;

    const float* Qg = gQ + (size_t)qb * BLKSZ * (NH * HD) + h * HD;
    const float* Kg = gK + (h >> 2) * HD;
    const float* Vg = gV + (h >> 2) * HD;

    float4* sQ4 = (float4*)sQ;
    float4* sK4 = (float4*)sK;
    float4* sV4 = (float4*)sV;

    // Load Q tile (pre-scaled, swizzled). Synced by the first loop-top barrier.
    for (int t = tid; t < 64 * 32; t += 256) {
        int row = t >> 5, g = t & 31;
        float4 v = *(const float4*)(Qg + (size_t)row * (NH * HD) + g * 4);
        v.x *= QSCALE; v.y *= QSCALE; v.z *= QSCALE; v.w *= QSCALE;
        sQ4[row * 32 + (g ^ (row & 7))] = v;
    }

    float m[4], l[4];
    u64 acc[4][4];   // packed f32x2 pairs of O columns
    #pragma unroll
    for (int i = 0; i < 4; i++) {
        m[i] = -INFINITY; l[i] = 0.f;
        #pragma unroll
        for (int k = 0; k < 4; k++) acc[i][k] = 0ull;
    }

    for (int kb = 0; kb <= qb; kb++) {
        // blocksparse mask: local window OR strided vertical (per-head offset)
        if (!((qb - kb) < LOCALB || ((kb + h + 1) % VERTS) == 0)) continue;

        __syncthreads();   // protects sQ (first iter) and sK/sV/sP reuse
        const float* Kp = Kg + (size_t)kb * BLKSZ * (NKV * HD);
        const float* Vp = Vg + (size_t)kb * BLKSZ * (NKV * HD);
        for (int t = tid; t < 64 * 32; t += 256) {
            int row = t >> 5, g = t & 31;
            int sidx = row * 32 + (g ^ (row & 7));
            sK4[sidx] = *(const float4*)(Kp + (size_t)row * (NKV * HD) + g * 4);
            sV4[sidx] = *(const float4*)(Vp + (size_t)row * (NKV * HD) + g * 4);
        }
        __syncthreads();

        // ---- S = (Q*scale) K^T : 4x4 per thread, f32x2 pair-accumulate over d ----
        u64 s2[4][4];
        #pragma unroll
        for (int i = 0; i < 4; i++)
            #pragma unroll
            for (int j = 0; j < 4; j++) s2[i][j] = 0ull;

        const ulonglong2* sQ2 = (const ulonglong2*)sQ;
        const ulonglong2* sK2 = (const ulonglong2*)sK;
        const int ksw = tx & 7;

        #pragma unroll 4
        for (int d4 = 0; d4 < 32; d4++) {
            ulonglong2 qv[4], kv[4];
            #pragma unroll
            for (int i = 0; i < 4; i++) {
                int r = ty * 4 + i;
                qv[i] = sQ2[r * 32 + (d4 ^ (r & 7))];
            }
            #pragma unroll
            for (int j = 0; j < 4; j++) {
                int c = tx + 16 * j;
                kv[j] = sK2[c * 32 + (d4 ^ ksw)];
            }
            #pragma unroll
            for (int i = 0; i < 4; i++)
                #pragma unroll
                for (int j = 0; j < 4; j++) {
                    s2[i][j] = ffma2(qv[i].x, kv[j].x, s2[i][j]);
                    s2[i][j] = ffma2(qv[i].y, kv[j].y, s2[i][j]);
                }
        }

        float sc[4][4];
        #pragma unroll
        for (int i = 0; i < 4; i++)
            #pragma unroll
            for (int j = 0; j < 4; j++) {
                float a, b; unpack2(s2[i][j], a, b); sc[i][j] = a + b;
            }

        // causal mask inside the diagonal block only
        if (kb == qb) {
            #pragma unroll
            for (int i = 0; i < 4; i++) {
                int qi = ty * 4 + i;
                #pragma unroll
                for (int j = 0; j < 4; j++) {
                    int kj = tx + 16 * j;
                    if (kj > qi) sc[i][j] = -INFINITY;
                }
            }
        }

        // ---- online softmax update (row groups = 16 consecutive lanes) ----
        #pragma unroll
        for (int i = 0; i < 4; i++) {
            float mb = fmaxf(fmaxf(sc[i][0], sc[i][1]), fmaxf(sc[i][2], sc[i][3]));
            #pragma unroll
            for (int o = 8; o; o >>= 1)
                mb = fmaxf(mb, __shfl_xor_sync(0xffffffffu, mb, o));
            float mn   = fmaxf(m[i], mb);
            float corr = __expf(m[i] - mn);
            m[i] = mn;
            float lb = 0.f;
            #pragma unroll
            for (int j = 0; j < 4; j++) {
                float p = __expf(sc[i][j] - mn);
                sc[i][j] = p; lb += p;
            }
            #pragma unroll
            for (int o = 8; o; o >>= 1)
                lb += __shfl_xor_sync(0xffffffffu, lb, o);
            l[i] = l[i] * corr + lb;
            u64 c2 = pack2(corr, corr);
            #pragma unroll
            for (int k = 0; k < 4; k++) acc[i][k] = fmul2(acc[i][k], c2);
        }

        // ---- write P (swizzled) ----
        #pragma unroll
        for (int i = 0; i < 4; i++) {
            int r = ty * 4 + i;
            #pragma unroll
            for (int j = 0; j < 4; j++) {
                int c = tx + 16 * j;
                sP[r * 64 + (((c >> 2) ^ (r & 7)) << 2) + (c & 3)] = sc[i][j];
            }
        }
        __syncthreads();

        // ---- O += P V : 4x8 per thread, f32x2 over column pairs ----
        const float4*     sP4 = (const float4*)sP;
        const ulonglong2* sV2 = (const ulonglong2*)sV;
        #pragma unroll 2
        for (int j4 = 0; j4 < 16; j4++) {
            float4 p4[4];
            #pragma unroll
            for (int i = 0; i < 4; i++) {
                int r = ty * 4 + i;
                p4[i] = sP4[r * 16 + (j4 ^ (r & 7))];
            }
            #pragma unroll
            for (int jj = 0; jj < 4; jj++) {
                int j = j4 * 4 + jj;
                ulonglong2 v0 = sV2[j * 32 + (tx ^ (j & 7))];
                ulonglong2 v1 = sV2[j * 32 + ((tx + 16) ^ (j & 7))];
                #pragma unroll
                for (int i = 0; i < 4; i++) {
                    float p = (jj == 0) ? p4[i].x : (jj == 1) ? p4[i].y
                            : (jj == 2) ? p4[i].z : p4[i].w;
                    u64 pp = pack2(p, p);
                    acc[i][0] = ffma2(pp, v0.x, acc[i][0]);
                    acc[i][1] = ffma2(pp, v0.y, acc[i][1]);
                    acc[i][2] = ffma2(pp, v1.x, acc[i][2]);
                    acc[i][3] = ffma2(pp, v1.y, acc[i][3]);
                }
            }
        }
    }

    // ---- epilogue: normalize and store ----
    #pragma unroll
    for (int i = 0; i < 4; i++) {
        float inv = 1.0f / l[i];
        float o[8];
        unpack2(acc[i][0], o[0], o[1]);
        unpack2(acc[i][1], o[2], o[3]);
        unpack2(acc[i][2], o[4], o[5]);
        unpack2(acc[i][3], o[6], o[7]);
        int row = qb * BLKSZ + ty * 4 + i;
        float* outp = gO + (size_t)row * (NH * HD) + h * HD;
        float4 w0 = make_float4(o[0] * inv, o[1] * inv, o[2] * inv, o[3] * inv);
        float4 w1 = make_float4(o[4] * inv, o[5] * inv, o[6] * inv, o[7] * inv);
        *(float4*)(outp + tx * 4)      = w0;
        *(float4*)(outp + 64 + tx * 4) = w1;
    }
}

extern "C" void kernel_launch(void* const* d_in, const int* in_sizes, int n_in,
                              void* d_out, int out_size) {
    const float* q = (const float*)d_in[0];
    const float* k = (const float*)d_in[1];
    const float* v = (const float*)d_in[2];
    float* o = (float*)d_out;

    const int smem_bytes = (8192 * 3 + 4096) * sizeof(float);  // 114688
    cudaFuncSetAttribute(bsattn_kernel,
                         cudaFuncAttributeMaxDynamicSharedMemorySize, smem_bytes);
    bsattn_kernel<<<dim3(NB, NH), 256, smem_bytes>>>(q, k, v, o);
}

// round 8
// speedup vs baseline: 1.0046x; 1.0046x over previous
#include <cuda_runtime.h>

#define NTOK   2048
#define NH     32
#define NKV    8
#define HD     128
#define BLKSZ  64
#define LOCALB 16
#define VERTS  8
#define NB     (NTOK/BLKSZ)
#define QSCALE 0.08838834764831845f

typedef unsigned long long u64;

__device__ __forceinline__ u64 pack2(float lo, float hi) {
    u64 r; asm("mov.b64 %0, {%1,%2};" : "=l"(r) : "f"(lo), "f"(hi)); return r;
}
__device__ __forceinline__ void unpack2(u64 v, float& lo, float& hi) {
    asm("mov.b64 {%0,%1}, %2;" : "=f"(lo), "=f"(hi) : "l"(v));
}
__device__ __forceinline__ u64 ffma2(u64 a, u64 b, u64 c) {
    u64 d; asm("fma.rn.f32x2 %0, %1, %2, %3;" : "=l"(d) : "l"(a), "l"(b), "l"(c)); return d;
}
__device__ __forceinline__ u64 fmul2(u64 a, u64 b) {
    u64 d; asm("mul.rn.f32x2 %0, %1, %2;" : "=l"(d) : "l"(a), "l"(b)); return d;
}

// One CTA = one (head, query-block). 256 threads as 16x16 grid:
//   ty = tid>>4 owns S/O rows ty*4..ty*4+3
//   tx = tid&15 owns S cols {tx, tx+16, tx+32, tx+48}, O cols {4tx..4tx+3, 64+4tx..64+4tx+3}
// Q/K/V/P tiles live in smem with a 16B-granule XOR swizzle (granule ^ (row&7))
// so all LDS.128 in both GEMMs are bank-conflict-free.
__global__ void __launch_bounds__(256, 2)
bsattn_kernel(const float* __restrict__ gQ, const float* __restrict__ gK,
              const float* __restrict__ gV, float* __restrict__ gO)
{
    extern __shared__ float smem[];
    float* sQ = smem;           // 64*128
    float* sK = sQ + 8192;      // 64*128
    float* sV = sK + 8192;      // 64*128
    float* sP = sV + 8192;      // 64*64

    const int qb  = blockIdx.x;
    const int h   = blockIdx.y;
    const int tid = threadIdx.x;
    const int ty  = tid >> 4;
    const int tx  = tid & 15;

    const float* Qg = gQ + (size_t)qb * BLKSZ * (NH * HD) + h * HD;
    const float* Kg = gK + (h >> 2) * HD;
    const float* Vg = gV + (h >> 2) * HD;

    float4* sQ4 = (float4*)sQ;
    float4* sK4 = (float4*)sK;
    float4* sV4 = (float4*)sV;

    // Load Q tile (pre-scaled, swizzled). Synced by the first loop-top barrier.
    for (int t = tid; t < 64 * 32; t += 256) {
        int row = t >> 5, g = t & 31;
        float4 v = *(const float4*)(Qg + (size_t)row * (NH * HD) + g * 4);
        v.x *= QSCALE; v.y *= QSCALE; v.z *= QSCALE; v.w *= QSCALE;
        sQ4[row * 32 + (g ^ (row & 7))] = v;
    }

    float m[4], l[4];
    u64 acc[4][4];   // packed f32x2 pairs of O columns
    #pragma unroll
    for (int i = 0; i < 4; i++) {
        m[i] = -INFINITY; l[i] = 0.f;
        #pragma unroll
        for (int k = 0; k < 4; k++) acc[i][k] = 0ull;
    }

    for (int kb = 0; kb <= qb; kb++) {
        // blocksparse mask: local window OR strided vertical (per-head offset)
        if (!((qb - kb) < LOCALB || ((kb + h + 1) % VERTS) == 0)) continue;

        __syncthreads();   // protects sQ (first iter) and sK/sV/sP reuse
        const float* Kp = Kg + (size_t)kb * BLKSZ * (NKV * HD);
        const float* Vp = Vg + (size_t)kb * BLKSZ * (NKV * HD);
        for (int t = tid; t < 64 * 32; t += 256) {
            int row = t >> 5, g = t & 31;
            int sidx = row * 32 + (g ^ (row & 7));
            sK4[sidx] = *(const float4*)(Kp + (size_t)row * (NKV * HD) + g * 4);
            sV4[sidx] = *(const float4*)(Vp + (size_t)row * (NKV * HD) + g * 4);
        }
        __syncthreads();

        // ---- S = (Q*scale) K^T : 4x4 per thread, f32x2 pair-accumulate over d ----
        u64 s2[4][4];
        #pragma unroll
        for (int i = 0; i < 4; i++)
            #pragma unroll
            for (int j = 0; j < 4; j++) s2[i][j] = 0ull;

        const ulonglong2* sQ2 = (const ulonglong2*)sQ;
        const ulonglong2* sK2 = (const ulonglong2*)sK;
        const int ksw = tx & 7;

        #pragma unroll 4
        for (int d4 = 0; d4 < 32; d4++) {
            ulonglong2 qv[4], kv[4];
            #pragma unroll
            for (int i = 0; i < 4; i++) {
                int r = ty * 4 + i;
                qv[i] = sQ2[r * 32 + (d4 ^ (r & 7))];
            }
            #pragma unroll
            for (int j = 0; j < 4; j++) {
                int c = tx + 16 * j;
                kv[j] = sK2[c * 32 + (d4 ^ ksw)];
            }
            #pragma unroll
            for (int i = 0; i < 4; i++)
                #pragma unroll
                for (int j = 0; j < 4; j++) {
                    s2[i][j] = ffma2(qv[i].x, kv[j].x, s2[i][j]);
                    s2[i][j] = ffma2(qv[i].y, kv[j].y, s2[i][j]);
                }
        }

        float sc[4][4];
        #pragma unroll
        for (int i = 0; i < 4; i++)
            #pragma unroll
            for (int j = 0; j < 4; j++) {
                float a, b; unpack2(s2[i][j], a, b); sc[i][j] = a + b;
            }

        // causal mask inside the diagonal block only
        if (kb == qb) {
            #pragma unroll
            for (int i = 0; i < 4; i++) {
                int qi = ty * 4 + i;
                #pragma unroll
                for (int j = 0; j < 4; j++) {
                    int kj = tx + 16 * j;
                    if (kj > qi) sc[i][j] = -INFINITY;
                }
            }
        }

        // ---- online softmax update (row groups = 16 consecutive lanes) ----
        #pragma unroll
        for (int i = 0; i < 4; i++) {
            float mb = fmaxf(fmaxf(sc[i][0], sc[i][1]), fmaxf(sc[i][2], sc[i][3]));
            #pragma unroll
            for (int o = 8; o; o >>= 1)
                mb = fmaxf(mb, __shfl_xor_sync(0xffffffffu, mb, o));
            float mn   = fmaxf(m[i], mb);
            float corr = __expf(m[i] - mn);
            m[i] = mn;
            float lb = 0.f;
            #pragma unroll
            for (int j = 0; j < 4; j++) {
                float p = __expf(sc[i][j] - mn);
                sc[i][j] = p; lb += p;
            }
            #pragma unroll
            for (int o = 8; o; o >>= 1)
                lb += __shfl_xor_sync(0xffffffffu, lb, o);
            l[i] = l[i] * corr + lb;
            u64 c2 = pack2(corr, corr);
            #pragma unroll
            for (int k = 0; k < 4; k++) acc[i][k] = fmul2(acc[i][k], c2);
        }

        // ---- write P (swizzled) ----
        #pragma unroll
        for (int i = 0; i < 4; i++) {
            int r = ty * 4 + i;
            #pragma unroll
            for (int j = 0; j < 4; j++) {
                int c = tx + 16 * j;
                sP[r * 64 + (((c >> 2) ^ (r & 7)) << 2) + (c & 3)] = sc[i][j];
            }
        }
        __syncthreads();

        // ---- O += P V : 4x8 per thread, f32x2 over column pairs ----
        const float4*     sP4 = (const float4*)sP;
        const ulonglong2* sV2 = (const ulonglong2*)sV;
        #pragma unroll 2
        for (int j4 = 0; j4 < 16; j4++) {
            float4 p4[4];
            #pragma unroll
            for (int i = 0; i < 4; i++) {
                int r = ty * 4 + i;
                p4[i] = sP4[r * 16 + (j4 ^ (r & 7))];
            }
            #pragma unroll
            for (int jj = 0; jj < 4; jj++) {
                int j = j4 * 4 + jj;
                ulonglong2 v0 = sV2[j * 32 + (tx ^ (j & 7))];
                ulonglong2 v1 = sV2[j * 32 + ((tx + 16) ^ (j & 7))];
                #pragma unroll
                for (int i = 0; i < 4; i++) {
                    float p = (jj == 0) ? p4[i].x : (jj == 1) ? p4[i].y
                            : (jj == 2) ? p4[i].z : p4[i].w;
                    u64 pp = pack2(p, p);
                    acc[i][0] = ffma2(pp, v0.x, acc[i][0]);
                    acc[i][1] = ffma2(pp, v0.y, acc[i][1]);
                    acc[i][2] = ffma2(pp, v1.x, acc[i][2]);
                    acc[i][3] = ffma2(pp, v1.y, acc[i][3]);
                }
            }
        }
    }

    // ---- epilogue: normalize and store ----
    #pragma unroll
    for (int i = 0; i < 4; i++) {
        float inv = 1.0f / l[i];
        float o[8];
        unpack2(acc[i][0], o[0], o[1]);
        unpack2(acc[i][1], o[2], o[3]);
        unpack2(acc[i][2], o[4], o[5]);
        unpack2(acc[i][3], o[6], o[7]);
        int row = qb * BLKSZ + ty * 4 + i;
        float* outp = gO + (size_t)row * (NH * HD) + h * HD;
        float4 w0 = make_float4(o[0] * inv, o[1] * inv, o[2] * inv, o[3] * inv);
        float4 w1 = make_float4(o[4] * inv, o[5] * inv, o[6] * inv, o[7] * inv);
        *(float4*)(outp + tx * 4)      = w0;
        *(float4*)(outp + 64 + tx * 4) = w1;
    }
}

extern "C" void kernel_launch(void* const* d_in, const int* in_sizes, int n_in,
                              void* d_out, int out_size) {
    const float* q = (const float*)d_in[0];
    const float* k = (const float*)d_in[1];
    const float* v = (const float*)d_in[2];
    float* o = (float*)d_out;

    const int smem_bytes = (8192 * 3 + 4096) * sizeof(float);  // 114688
    cudaFuncSetAttribute(bsattn_kernel,
                         cudaFuncAttributeMaxDynamicSharedMemorySize, smem_bytes);
    bsattn_kernel<<<dim3(NB, NH), 256, smem_bytes>>>(q, k, v, o);
}

// round 9
// speedup vs baseline: 1.0068x; 1.0023x over previous
#include <cuda_runtime.h>

#define NTOK   2048
#define NH     32
#define NKV    8
#define HD     128
#define BLKSZ  64
#define LOCALB 16
#define VERTS  8
#define NB     (NTOK/BLKSZ)
#define QSCALE 0.08838834764831845f

typedef unsigned long long u64;

__device__ __forceinline__ u64 pack2(float lo, float hi) {
    u64 r; asm("mov.b64 %0, {%1,%2};" : "=l"(r) : "f"(lo), "f"(hi)); return r;
}
__device__ __forceinline__ void unpack2(u64 v, float& lo, float& hi) {
    asm("mov.b64 {%0,%1}, %2;" : "=f"(lo), "=f"(hi) : "l"(v));
}
__device__ __forceinline__ u64 ffma2(u64 a, u64 b, u64 c) {
    u64 d; asm("fma.rn.f32x2 %0, %1, %2, %3;" : "=l"(d) : "l"(a), "l"(b), "l"(c)); return d;
}
__device__ __forceinline__ u64 fmul2(u64 a, u64 b) {
    u64 d; asm("mul.rn.f32x2 %0, %1, %2;" : "=l"(d) : "l"(a), "l"(b)); return d;
}

// One CTA = one (head, query-block). 256 threads as 16x16 grid:
//   ty = tid>>4 owns S/O rows ty*4..ty*4+3
//   tx = tid&15 owns S cols {tx, tx+16, tx+32, tx+48}, O cols {4tx..4tx+3, 64+4tx..64+4tx+3}
// Q/K/V/P tiles live in smem with a 16B-granule XOR swizzle (granule ^ (row&7))
// so all LDS.128 in both GEMMs are bank-conflict-free.
__global__ void __launch_bounds__(256, 2)
bsattn_kernel(const float* __restrict__ gQ, const float* __restrict__ gK,
              const float* __restrict__ gV, float* __restrict__ gO)
{
    extern __shared__ float smem[];
    float* sQ = smem;           // 64*128
    float* sK = sQ + 8192;      // 64*128
    float* sV = sK + 8192;      // 64*128
    float* sP = sV + 8192;      // 64*64

    const int qb  = blockIdx.x;
    const int h   = blockIdx.y;
    const int tid = threadIdx.x;
    const int ty  = tid >> 4;
    const int tx  = tid & 15;

    const float* Qg = gQ + (size_t)qb * BLKSZ * (NH * HD) + h * HD;
    const float* Kg = gK + (h >> 2) * HD;
    const float* Vg = gV + (h >> 2) * HD;

    float4* sQ4 = (float4*)sQ;
    float4* sK4 = (float4*)sK;
    float4* sV4 = (float4*)sV;

    // Load Q tile (pre-scaled, swizzled). Synced by the first loop-top barrier.
    for (int t = tid; t < 64 * 32; t += 256) {
        int row = t >> 5, g = t & 31;
        float4 v = *(const float4*)(Qg + (size_t)row * (NH * HD) + g * 4);
        v.x *= QSCALE; v.y *= QSCALE; v.z *= QSCALE; v.w *= QSCALE;
        sQ4[row * 32 + (g ^ (row & 7))] = v;
    }

    float m[4], l[4];
    u64 acc[4][4];   // packed f32x2 pairs of O columns
    #pragma unroll
    for (int i = 0; i < 4; i++) {
        m[i] = -INFINITY; l[i] = 0.f;
        #pragma unroll
        for (int k = 0; k < 4; k++) acc[i][k] = 0ull;
    }

    for (int kb = 0; kb <= qb; kb++) {
        // blocksparse mask: local window OR strided vertical (per-head offset)
        if (!((qb - kb) < LOCALB || ((kb + h + 1) % VERTS) == 0)) continue;

        __syncthreads();   // protects sQ (first iter) and sK/sV/sP reuse
        const float* Kp = Kg + (size_t)kb * BLKSZ * (NKV * HD);
        const float* Vp = Vg + (size_t)kb * BLKSZ * (NKV * HD);
        for (int t = tid; t < 64 * 32; t += 256) {
            int row = t >> 5, g = t & 31;
            int sidx = row * 32 + (g ^ (row & 7));
            sK4[sidx] = *(const float4*)(Kp + (size_t)row * (NKV * HD) + g * 4);
            sV4[sidx] = *(const float4*)(Vp + (size_t)row * (NKV * HD) + g * 4);
        }
        __syncthreads();

        // ---- S = (Q*scale) K^T : 4x4 per thread, f32x2 pair-accumulate over d ----
        u64 s2[4][4];
        #pragma unroll
        for (int i = 0; i < 4; i++)
            #pragma unroll
            for (int j = 0; j < 4; j++) s2[i][j] = 0ull;

        const ulonglong2* sQ2 = (const ulonglong2*)sQ;
        const ulonglong2* sK2 = (const ulonglong2*)sK;
        const int ksw = tx & 7;

        #pragma unroll 4
        for (int d4 = 0; d4 < 32; d4++) {
            ulonglong2 qv[4], kv[4];
            #pragma unroll
            for (int i = 0; i < 4; i++) {
                int r = ty * 4 + i;
                qv[i] = sQ2[r * 32 + (d4 ^ (r & 7))];
            }
            #pragma unroll
            for (int j = 0; j < 4; j++) {
                int c = tx + 16 * j;
                kv[j] = sK2[c * 32 + (d4 ^ ksw)];
            }
            #pragma unroll
            for (int i = 0; i < 4; i++)
                #pragma unroll
                for (int j = 0; j < 4; j++) {
                    s2[i][j] = ffma2(qv[i].x, kv[j].x, s2[i][j]);
                    s2[i][j] = ffma2(qv[i].y, kv[j].y, s2[i][j]);
                }
        }

        float sc[4][4];
        #pragma unroll
        for (int i = 0; i < 4; i++)
            #pragma unroll
            for (int j = 0; j < 4; j++) {
                float a, b; unpack2(s2[i][j], a, b); sc[i][j] = a + b;
            }

        // causal mask inside the diagonal block only
        if (kb == qb) {
            #pragma unroll
            for (int i = 0; i < 4; i++) {
                int qi = ty * 4 + i;
                #pragma unroll
                for (int j = 0; j < 4; j++) {
                    int kj = tx + 16 * j;
                    if (kj > qi) sc[i][j] = -INFINITY;
                }
            }
        }

        // ---- online softmax update (row groups = 16 consecutive lanes) ----
        #pragma unroll
        for (int i = 0; i < 4; i++) {
            float mb = fmaxf(fmaxf(sc[i][0], sc[i][1]), fmaxf(sc[i][2], sc[i][3]));
            #pragma unroll
            for (int o = 8; o; o >>= 1)
                mb = fmaxf(mb, __shfl_xor_sync(0xffffffffu, mb, o));
            float mn   = fmaxf(m[i], mb);
            float corr = __expf(m[i] - mn);
            m[i] = mn;
            float lb = 0.f;
            #pragma unroll
            for (int j = 0; j < 4; j++) {
                float p = __expf(sc[i][j] - mn);
                sc[i][j] = p; lb += p;
            }
            #pragma unroll
            for (int o = 8; o; o >>= 1)
                lb += __shfl_xor_sync(0xffffffffu, lb, o);
            l[i] = l[i] * corr + lb;
            u64 c2 = pack2(corr, corr);
            #pragma unroll
            for (int k = 0; k < 4; k++) acc[i][k] = fmul2(acc[i][k], c2);
        }

        // ---- write P (swizzled) ----
        #pragma unroll
        for (int i = 0; i < 4; i++) {
            int r = ty * 4 + i;
            #pragma unroll
            for (int j = 0; j < 4; j++) {
                int c = tx + 16 * j;
                sP[r * 64 + (((c >> 2) ^ (r & 7)) << 2) + (c & 3)] = sc[i][j];
            }
        }
        __syncthreads();

        // ---- O += P V : 4x8 per thread, f32x2 over column pairs ----
        const float4*     sP4 = (const float4*)sP;
        const ulonglong2* sV2 = (const ulonglong2*)sV;
        #pragma unroll 2
        for (int j4 = 0; j4 < 16; j4++) {
            float4 p4[4];
            #pragma unroll
            for (int i = 0; i < 4; i++) {
                int r = ty * 4 + i;
                p4[i] = sP4[r * 16 + (j4 ^ (r & 7))];
            }
            #pragma unroll
            for (int jj = 0; jj < 4; jj++) {
                int j = j4 * 4 + jj;
                ulonglong2 v0 = sV2[j * 32 + (tx ^ (j & 7))];
                ulonglong2 v1 = sV2[j * 32 + ((tx + 16) ^ (j & 7))];
                #pragma unroll
                for (int i = 0; i < 4; i++) {
                    float p = (jj == 0) ? p4[i].x : (jj == 1) ? p4[i].y
                            : (jj == 2) ? p4[i].z : p4[i].w;
                    u64 pp = pack2(p, p);
                    acc[i][0] = ffma2(pp, v0.x, acc[i][0]);
                    acc[i][1] = ffma2(pp, v0.y, acc[i][1]);
                    acc[i][2] = ffma2(pp, v1.x, acc[i][2]);
                    acc[i][3] = ffma2(pp, v1.y, acc[i][3]);
                }
            }
        }
    }

    // ---- epilogue: normalize and store ----
    #pragma unroll
    for (int i = 0; i < 4; i++) {
        float inv = 1.0f / l[i];
        float o[8];
        unpack2(acc[i][0], o[0], o[1]);
        unpack2(acc[i][1], o[2], o[3]);
        unpack2(acc[i][2], o[4], o[5]);
        unpack2(acc[i][3], o[6], o[7]);
        int row = qb * BLKSZ + ty * 4 + i;
        float* outp = gO + (size_t)row * (NH * HD) + h * HD;
        float4 w0 = make_float4(o[0] * inv, o[1] * inv, o[2] * inv, o[3] * inv);
        float4 w1 = make_float4(o[4] * inv, o[5] * inv, o[6] * inv, o[7] * inv);
        *(float4*)(outp + tx * 4)      = w0;
        *(float4*)(outp + 64 + tx * 4) = w1;
    }
}

extern "C" void kernel_launch(void* const* d_in, const int* in_sizes, int n_in,
                              void* d_out, int out_size) {
    const float* q = (const float*)d_in[0];
    const float* k = (const float*)d_in[1];
    const float* v = (const float*)d_in[2];
    float* o = (float*)d_out;

    const int smem_bytes = (8192 * 3 + 4096) * sizeof(float);  // 114688
    cudaFuncSetAttribute(bsattn_kernel,
                         cudaFuncAttributeMaxDynamicSharedMemorySize, smem_bytes);
    bsattn_kernel<<<dim3(NB, NH), 256, smem_bytes>>>(q, k, v, o);
}

// round 10
// speedup vs baseline: 1.0185x; 1.0116x over previous
#include <cuda_runtime.h>

#define NTOK   2048
#define NH     32
#define NKV    8
#define HD     128
#define BLKSZ  64
#define LOCALB 16
#define VERTS  8
#define NB     (NTOK/BLKSZ)
#define QSCALE 0.08838834764831845f

typedef unsigned long long u64;

__device__ __forceinline__ u64 pack2(float lo, float hi) {
    u64 r; asm("mov.b64 %0, {%1,%2};" : "=l"(r) : "f"(lo), "f"(hi)); return r;
}
__device__ __forceinline__ void unpack2(u64 v, float& lo, float& hi) {
    asm("mov.b64 {%0,%1}, %2;" : "=f"(lo), "=f"(hi) : "l"(v));
}
__device__ __forceinline__ u64 ffma2(u64 a, u64 b, u64 c) {
    u64 d; asm("fma.rn.f32x2 %0, %1, %2, %3;" : "=l"(d) : "l"(a), "l"(b), "l"(c)); return d;
}
__device__ __forceinline__ u64 fmul2(u64 a, u64 b) {
    u64 d; asm("mul.rn.f32x2 %0, %1, %2;" : "=l"(d) : "l"(a), "l"(b)); return d;
}

// One CTA = one (head, query-block). 256 threads as 16x16 grid:
//   ty = tid>>4 owns S/O rows ty*4..ty*4+3
//   tx = tid&15 owns S cols {tx, tx+16, tx+32, tx+48}, O cols {4tx..4tx+3, 64+4tx..64+4tx+3}
// Q/K/V/P tiles live in smem with a 16B-granule XOR swizzle (granule ^ (row&7))
// so all LDS.128 in both GEMMs are bank-conflict-free.
__global__ void __launch_bounds__(256, 2)
bsattn_kernel(const float* __restrict__ gQ, const float* __restrict__ gK,
              const float* __restrict__ gV, float* __restrict__ gO)
{
    extern __shared__ float smem[];
    float* sQ = smem;           // 64*128
    float* sK = sQ + 8192;      // 64*128
    float* sV = sK + 8192;      // 64*128
    float* sP = sV + 8192;      // 64*64

    const int qb  = blockIdx.x;
    const int h   = blockIdx.y;
    const int tid = threadIdx.x;
    const int ty  = tid >> 4;
    const int tx  = tid & 15;

    const float* Qg = gQ + (size_t)qb * BLKSZ * (NH * HD) + h * HD;
    const float* Kg = gK + (h >> 2) * HD;
    const float* Vg = gV + (h >> 2) * HD;

    float4* sQ4 = (float4*)sQ;
    float4* sK4 = (float4*)sK;
    float4* sV4 = (float4*)sV;

    // Load Q tile (pre-scaled, swizzled). Synced by the first loop-top barrier.
    for (int t = tid; t < 64 * 32; t += 256) {
        int row = t >> 5, g = t & 31;
        float4 v = *(const float4*)(Qg + (size_t)row * (NH * HD) + g * 4);
        v.x *= QSCALE; v.y *= QSCALE; v.z *= QSCALE; v.w *= QSCALE;
        sQ4[row * 32 + (g ^ (row & 7))] = v;
    }

    float m[4], l[4];
    u64 acc[4][4];   // packed f32x2 pairs of O columns
    #pragma unroll
    for (int i = 0; i < 4; i++) {
        m[i] = -INFINITY; l[i] = 0.f;
        #pragma unroll
        for (int k = 0; k < 4; k++) acc[i][k] = 0ull;
    }

    for (int kb = 0; kb <= qb; kb++) {
        // blocksparse mask: local window OR strided vertical (per-head offset)
        if (!((qb - kb) < LOCALB || ((kb + h + 1) % VERTS) == 0)) continue;

        __syncthreads();   // protects sQ (first iter) and sK/sV/sP reuse
        const float* Kp = Kg + (size_t)kb * BLKSZ * (NKV * HD);
        const float* Vp = Vg + (size_t)kb * BLKSZ * (NKV * HD);
        for (int t = tid; t < 64 * 32; t += 256) {
            int row = t >> 5, g = t & 31;
            int sidx = row * 32 + (g ^ (row & 7));
            sK4[sidx] = *(const float4*)(Kp + (size_t)row * (NKV * HD) + g * 4);
            sV4[sidx] = *(const float4*)(Vp + (size_t)row * (NKV * HD) + g * 4);
        }
        __syncthreads();

        // ---- S = (Q*scale) K^T : 4x4 per thread, f32x2 pair-accumulate over d ----
        u64 s2[4][4];
        #pragma unroll
        for (int i = 0; i < 4; i++)
            #pragma unroll
            for (int j = 0; j < 4; j++) s2[i][j] = 0ull;

        const ulonglong2* sQ2 = (const ulonglong2*)sQ;
        const ulonglong2* sK2 = (const ulonglong2*)sK;
        const int ksw = tx & 7;

        #pragma unroll 4
        for (int d4 = 0; d4 < 32; d4++) {
            ulonglong2 qv[4], kv[4];
            #pragma unroll
            for (int i = 0; i < 4; i++) {
                int r = ty * 4 + i;
                qv[i] = sQ2[r * 32 + (d4 ^ (r & 7))];
            }
            #pragma unroll
            for (int j = 0; j < 4; j++) {
                int c = tx + 16 * j;
                kv[j] = sK2[c * 32 + (d4 ^ ksw)];
            }
            #pragma unroll
            for (int i = 0; i < 4; i++)
                #pragma unroll
                for (int j = 0; j < 4; j++) {
                    s2[i][j] = ffma2(qv[i].x, kv[j].x, s2[i][j]);
                    s2[i][j] = ffma2(qv[i].y, kv[j].y, s2[i][j]);
                }
        }

        float sc[4][4];
        #pragma unroll
        for (int i = 0; i < 4; i++)
            #pragma unroll
            for (int j = 0; j < 4; j++) {
                float a, b; unpack2(s2[i][j], a, b); sc[i][j] = a + b;
            }

        // causal mask inside the diagonal block only
        if (kb == qb) {
            #pragma unroll
            for (int i = 0; i < 4; i++) {
                int qi = ty * 4 + i;
                #pragma unroll
                for (int j = 0; j < 4; j++) {
                    int kj = tx + 16 * j;
                    if (kj > qi) sc[i][j] = -INFINITY;
                }
            }
        }

        // ---- online softmax update (row groups = 16 consecutive lanes) ----
        #pragma unroll
        for (int i = 0; i < 4; i++) {
            float mb = fmaxf(fmaxf(sc[i][0], sc[i][1]), fmaxf(sc[i][2], sc[i][3]));
            #pragma unroll
            for (int o = 8; o; o >>= 1)
                mb = fmaxf(mb, __shfl_xor_sync(0xffffffffu, mb, o));
            float mn   = fmaxf(m[i], mb);
            float corr = __expf(m[i] - mn);
            m[i] = mn;
            float lb = 0.f;
            #pragma unroll
            for (int j = 0; j < 4; j++) {
                float p = __expf(sc[i][j] - mn);
                sc[i][j] = p; lb += p;
            }
            #pragma unroll
            for (int o = 8; o; o >>= 1)
                lb += __shfl_xor_sync(0xffffffffu, lb, o);
            l[i] = l[i] * corr + lb;
            u64 c2 = pack2(corr, corr);
            #pragma unroll
            for (int k = 0; k < 4; k++) acc[i][k] = fmul2(acc[i][k], c2);
        }

        // ---- write P (swizzled) ----
        #pragma unroll
        for (int i = 0; i < 4; i++) {
            int r = ty * 4 + i;
            #pragma unroll
            for (int j = 0; j < 4; j++) {
                int c = tx + 16 * j;
                sP[r * 64 + (((c >> 2) ^ (r & 7)) << 2) + (c & 3)] = sc[i][j];
            }
        }
        __syncthreads();

        // ---- O += P V : 4x8 per thread, f32x2 over column pairs ----
        const float4*     sP4 = (const float4*)sP;
        const ulonglong2* sV2 = (const ulonglong2*)sV;
        #pragma unroll 2
        for (int j4 = 0; j4 < 16; j4++) {
            float4 p4[4];
            #pragma unroll
            for (int i = 0; i < 4; i++) {
                int r = ty * 4 + i;
                p4[i] = sP4[r * 16 + (j4 ^ (r & 7))];
            }
            #pragma unroll
            for (int jj = 0; jj < 4; jj++) {
                int j = j4 * 4 + jj;
                ulonglong2 v0 = sV2[j * 32 + (tx ^ (j & 7))];
                ulonglong2 v1 = sV2[j * 32 + ((tx + 16) ^ (j & 7))];
                #pragma unroll
                for (int i = 0; i < 4; i++) {
                    float p = (jj == 0) ? p4[i].x : (jj == 1) ? p4[i].y
                            : (jj == 2) ? p4[i].z : p4[i].w;
                    u64 pp = pack2(p, p);
                    acc[i][0] = ffma2(pp, v0.x, acc[i][0]);
                    acc[i][1] = ffma2(pp, v0.y, acc[i][1]);
                    acc[i][2] = ffma2(pp, v1.x, acc[i][2]);
                    acc[i][3] = ffma2(pp, v1.y, acc[i][3]);
                }
            }
        }
    }

    // ---- epilogue: normalize and store ----
    #pragma unroll
    for (int i = 0; i < 4; i++) {
        float inv = 1.0f / l[i];
        float o[8];
        unpack2(acc[i][0], o[0], o[1]);
        unpack2(acc[i][1], o[2], o[3]);
        unpack2(acc[i][2], o[4], o[5]);
        unpack2(acc[i][3], o[6], o[7]);
        int row = qb * BLKSZ + ty * 4 + i;
        float* outp = gO + (size_t)row * (NH * HD) + h * HD;
        float4 w0 = make_float4(o[0] * inv, o[1] * inv, o[2] * inv, o[3] * inv);
        float4 w1 = make_float4(o[4] * inv, o[5] * inv, o[6] * inv, o[7] * inv);
        *(float4*)(outp + tx * 4)      = w0;
        *(float4*)(outp + 64 + tx * 4) = w1;
    }
}

extern "C" void kernel_launch(void* const* d_in, const int* in_sizes, int n_in,
                              void* d_out, int out_size) {
    const float* q = (const float*)d_in[0];
    const float* k = (const float*)d_in[1];
    const float* v = (const float*)d_in[2];
    float* o = (float*)d_out;

    const int smem_bytes = (8192 * 3 + 4096) * sizeof(float);  // 114688
    cudaFuncSetAttribute(bsattn_kernel,
                         cudaFuncAttributeMaxDynamicSharedMemorySize, smem_bytes);
    bsattn_kernel<<<dim3(NB, NH), 256, smem_bytes>>>(q, k, v, o);
}